// round 16
// baseline (speedup 1.0000x reference)
#include <cuda_runtime.h>

// ---------------- problem sizes ----------------
#define NC 100000
#define NT 300000
#define NP 50000
#define EM 300000
#define EI 600000
#define ET (EM + EI)
#define NOUT 10

#define NTHR 256
#define CTAS_PER_SM 6

// ---------------- scratch layout ----------------
#define OFF_MCS   0                               // [NC*8]
#define OFF_MPS   (OFF_MCS + (size_t)NC * 8)      // [NP*8]
#define OFF_CMC   (OFF_MPS + (size_t)NP * 8)      // [NC]
#define OFF_CIP   (OFF_CMC + NC)                  // [NP]
#define OFF_CMT   (OFF_CIP + NP)                  // [NT]
#define OFF_CIT   (OFF_CMT + NT)                  // [NT]
#define ZONEA_END (OFF_CIT + NT)
#define OFF_ZC    ZONEA_END                       // [NT*12]
#define OFF_ZP    (OFF_ZC + (size_t)NT * 12)      // [NT*12]
#define SCR_TOTAL (OFF_ZP + (size_t)NT * 12)

__device__ float g_scr[SCR_TOTAL];
__device__ float g_yc[(size_t)NC * 12];
__device__ float g_yp[(size_t)NP * 12];
__device__ unsigned g_bar;

__device__ float g_m1[7][1024];
__device__ float g_r1[7][128];
__device__ float g_MW[3][1280];
__device__ float g_G[400];
__device__ float g_g[50];

// ---------------- grid barrier (target scales with gridDim.x) ----------------
__device__ __forceinline__ void gbar(int phase) {
    __syncthreads();
    if (threadIdx.x == 0) {
        __threadfence();
        atomicAdd(&g_bar, 1u);
        unsigned target = (unsigned)phase * gridDim.x;
        while (*(volatile unsigned*)&g_bar < target) { __nanosleep(64); }
        __threadfence();
    }
    __syncthreads();
}

// ---------------- atomics ----------------
__device__ __forceinline__ void red_add_v4(float* addr, float a, float b, float c, float d) {
    asm volatile("red.global.add.v4.f32 [%0], {%1,%2,%3,%4};"
                 :: "l"(addr), "f"(a), "f"(b), "f"(c), "f"(d) : "memory");
}
__device__ __forceinline__ void red_add_v2(float* addr, float a, float b) {
    asm volatile("red.global.add.v2.f32 [%0], {%1,%2};"
                 :: "l"(addr), "f"(a), "f"(b) : "memory");
}
__device__ __forceinline__ void red_add_f(float* addr, float v) {
    asm volatile("red.global.add.f32 [%0], %1;" :: "l"(addr), "f"(v) : "memory");
}

// ---------------- prep1 ----------------
__device__ void prep1_block(int b, int col,
                            const float* __restrict__ Wc, const float* __restrict__ bc,
                            const float* __restrict__ Wn, const float* __restrict__ Wr,
                            const float* __restrict__ bl) {
    if (b < 7) {
        int X = 0; const float* M1 = Wn; const float* M2 = nullptr; float s = 1.f;
        switch (b) {
            case 0: X = 1; M1 = Wr;             M2 = Wr + 2 * 16384; s = 0.5f; break;
            case 1: X = 0; M1 = Wn;             s = 0.5f; break;
            case 2: X = 2; M1 = Wn + 2 * 16384; s = 0.5f; break;
            case 3: X = 0; M1 = Wr + 1 * 16384; break;
            case 4: X = 1; M1 = Wn + 1 * 16384; break;
            case 5: X = 2; M1 = Wr + 3 * 16384; break;
            case 6: X = 1; M1 = Wn + 3 * 16384; break;
        }
        for (int f = 0; f < 8; f++) {
            float acc = 0.f;
            #pragma unroll 4
            for (int d = 0; d < 16; d++) {
                int k = f * 16 + d;
                float m = M1[k * 128 + col];
                if (M2) m += M2[k * 128 + col];
                acc += Wc[X * 128 + k] * m;
            }
            g_m1[b][f * 128 + col] = s * acc;
        }
    } else {
        int r = b - 7;
        float acc = 0.f;
        switch (r) {
            case 0:
                for (int k = 0; k < 128; k++) acc += bc[k] * Wn[k * 128 + col];
                g_r1[0][col] = 0.5f * acc; break;
            case 1:
                for (int k = 0; k < 128; k++) acc += bc[256 + k] * Wn[2 * 16384 + k * 128 + col];
                g_r1[1][col] = 0.5f * acc; break;
            case 2:
                for (int k = 0; k < 128; k++)
                    acc += bc[128 + k] * (Wr[k * 128 + col] + Wr[2 * 16384 + k * 128 + col]);
                g_r1[2][col] = 0.5f * (acc + bl[0 * 128 + col] + bl[2 * 128 + col]); break;
            case 3:
                for (int k = 0; k < 128; k++) acc += bc[128 + k] * Wn[1 * 16384 + k * 128 + col];
                g_r1[3][col] = acc; break;
            case 4:
                for (int k = 0; k < 128; k++) acc += bc[k] * Wr[1 * 16384 + k * 128 + col];
                g_r1[4][col] = acc + bl[1 * 128 + col]; break;
            case 5:
                for (int k = 0; k < 128; k++) acc += bc[128 + k] * Wn[3 * 16384 + k * 128 + col];
                g_r1[5][col] = acc; break;
            case 6:
                for (int k = 0; k < 128; k++) acc += bc[256 + k] * Wr[3 * 16384 + k * 128 + col];
                g_r1[6][col] = acc + bl[3 * 128 + col]; break;
        }
    }
}

// ---------------- MW = 0.5*{Un, Vn, R0+R2} @ Wout ----------------
__device__ void mw_thread(int i, const float* __restrict__ Wn, const float* __restrict__ Wr,
                          const float* __restrict__ Wout) {
    int type = i / 1280;
    int rem  = i % 1280;
    int j = rem / 10, o = rem % 10;
    const float* Un = Wn + 4 * 16384;
    const float* Vn = Wn + 6 * 16384;
    const float* R0 = Wr + 4 * 16384;
    const float* R2 = Wr + 6 * 16384;
    float acc = 0.f;
    #pragma unroll 8
    for (int k = 0; k < 128; k++) {
        float m;
        if (type == 0)      m = Un[j * 128 + k];
        else if (type == 1) m = Vn[j * 128 + k];
        else                m = R0[j * 128 + k] + R2[j * 128 + k];
        acc += 0.5f * m * Wout[k * 10 + o];
    }
    g_MW[type][j * 10 + o] = acc;
}

// ---------------- G/g (warp-per-output) ----------------
__device__ void gg_warp(int w, int lane,
                        const float* __restrict__ bl, const float* __restrict__ Wout,
                        const float* __restrict__ bout) {
    float acc = 0.f;
    if (w < 400) {
        int m = w / 80, f = (w % 80) / 10, o = w % 10;
        for (int j = lane; j < 128; j += 32) {
            float v = 0.f;
            switch (m) {
                case 0: v = g_m1[0][f * 128 + j] * g_MW[2][j * 10 + o]; break;
                case 1: v = g_m1[3][f * 128 + j] * g_MW[0][j * 10 + o]
                          + g_m1[1][f * 128 + j] * g_MW[2][j * 10 + o]; break;
                case 2: v = g_m1[5][f * 128 + j] * g_MW[1][j * 10 + o]
                          + g_m1[2][f * 128 + j] * g_MW[2][j * 10 + o]; break;
                case 3: v = g_m1[4][f * 128 + j] * g_MW[0][j * 10 + o]; break;
                case 4: v = g_m1[6][f * 128 + j] * g_MW[1][j * 10 + o]; break;
            }
            acc += v;
        }
        #pragma unroll
        for (int off = 16; off > 0; off >>= 1) acc += __shfl_xor_sync(0xffffffffu, acc, off);
        if (lane == 0) g_G[(m * 8 + f) * 10 + o] = acc;
    } else if (w < 450) {
        int r = (w - 400) / 10, o = (w - 400) % 10;
        for (int j = lane; j < 128; j += 32) {
            float v = 0.f;
            switch (r) {
                case 0: v = g_r1[3][j] * g_MW[0][j * 10 + o]; break;
                case 1: v = g_r1[5][j] * g_MW[1][j * 10 + o]; break;
                case 2: v = g_r1[4][j] * g_MW[0][j * 10 + o] + g_r1[0][j] * g_MW[2][j * 10 + o]; break;
                case 3: v = g_r1[6][j] * g_MW[1][j * 10 + o] + g_r1[1][j] * g_MW[2][j * 10 + o]; break;
                case 4: v = g_r1[2][j] * g_MW[2][j * 10 + o]
                          + 0.5f * (bl[512 + j] + bl[768 + j]) * Wout[j * 10 + o]; break;
            }
            acc += v;
        }
        #pragma unroll
        for (int off = 16; off > 0; off >>= 1) acc += __shfl_xor_sync(0xffffffffu, acc, off);
        if (lane == 0) g_g[r * 10 + o] = acc + (r == 4 ? bout[o] : 0.f);
    }
}

// ---------------- persistent kernel (5 phases incl. final) ----------------
__global__ __launch_bounds__(NTHR, CTAS_PER_SM)
void fused(const float* __restrict__ x_c, const float* __restrict__ x_t,
           const float* __restrict__ x_p,
           const float* __restrict__ W_col, const float* __restrict__ b_col,
           const float* __restrict__ Wn, const float* __restrict__ Wr,
           const float* __restrict__ b_lin,
           const float* __restrict__ W_out, const float* __restrict__ b_out,
           const int* __restrict__ em_src, const int* __restrict__ em_dst,
           const int* __restrict__ ei_src, const int* __restrict__ ei_dst,
           float* __restrict__ out) {
    const int tid = threadIdx.x;
    const int bid = blockIdx.x;
    const int nbl = gridDim.x;
    float* scr = g_scr;
    __shared__ float sG[400];
    __shared__ float sg[50];

    // ---- P0: prep1 (0-13) | MW (14-28) | zero zone A (29+) ----
    if (bid < 14) {
        if (tid < 128) prep1_block(bid, tid, W_col, b_col, Wn, Wr, b_lin);
    } else if (bid < 29) {
        int i = (bid - 14) * NTHR + tid;
        if (i < 3840) mw_thread(i, Wn, Wr, W_out);
    } else {
        float4 z = make_float4(0.f, 0.f, 0.f, 0.f);
        float4* p = (float4*)scr;
        int n4 = (int)(ZONEA_END / 4);
        for (int i = (bid - 29) * NTHR + tid; i < n4; i += (nbl - 29) * NTHR) p[i] = z;
    }
    gbar(1);

    // ---- P1: zero zone B (rides free) + s-side scatter + degrees ; CTAs 0-56 compute G/g ----
    {
        float4 z = make_float4(0.f, 0.f, 0.f, 0.f);
        float4* p = (float4*)(scr + ZONEA_END);
        int n4 = (int)((SCR_TOTAL - ZONEA_END) / 4);
        for (int i = bid * NTHR + tid; i < n4; i += nbl * NTHR) p[i] = z;
    }
    if (bid < 57) {
        int w = bid * (NTHR / 32) + (tid >> 5);
        gg_warp(w, tid & 31, b_lin, W_out, b_out);
    } else {
        const int W1 = nbl - 57;
        for (int e0 = (bid - 57) * NTHR + tid; e0 < ET; e0 += W1 * NTHR) {
            int e = e0;
            const int *src, *dst;
            float *agg, *cnts, *cntd;
            if (e < EM) {
                src = em_src; dst = em_dst;
                agg = scr + OFF_MCS; cnts = scr + OFF_CMC; cntd = scr + OFF_CMT;
            } else {
                e -= EM;
                src = ei_src; dst = ei_dst;
                agg = scr + OFF_MPS; cnts = scr + OFF_CIP; cntd = scr + OFF_CIT;
            }
            int s = __ldg(src + e);
            int d = __ldg(dst + e);
            const float4* pd = (const float4*)(x_t + (size_t)d * 8);
            float4 b0 = pd[0], b1 = pd[1];
            float* os = agg + (size_t)s * 8;
            red_add_v4(os,     b0.x, b0.y, b0.z, b0.w);
            red_add_v4(os + 4, b1.x, b1.y, b1.z, b1.w);
            red_add_f(cnts + s, 1.0f);
            red_add_f(cntd + d, 1.0f);
        }
    }
    gbar(2);

    // ---- P1.5: load G/g to smem + per-node projection y ----
    for (int i = tid; i < 400; i += NTHR) sG[i] = g_G[i];
    if (tid < 50) sg[tid] = g_g[tid];
    __syncthreads();
    {
        int n = bid * NTHR + tid;
        if (n < NC + NP) {
            const float* xrow;
            const float* msum;
            const float* cnt;
            const float* Ga; const float* Gb;
            float* Y;
            int idx = n;
            if (n < NC) {
                xrow = x_c; msum = scr + OFF_MCS; cnt = scr + OFF_CMC;
                Ga = sG + 80;  Gb = sG + 240;
                Y = g_yc;
            } else {
                idx = n - NC;
                xrow = x_p; msum = scr + OFF_MPS; cnt = scr + OFF_CIP;
                Ga = sG + 160; Gb = sG + 320;
                Y = g_yp;
            }
            const float4* px = (const float4*)(xrow + (size_t)idx * 8);
            const float4* pm = (const float4*)(msum + (size_t)idx * 8);
            float4 xa = px[0], xb = px[1];
            float4 ma = pm[0], mb = pm[1];
            float iv = 1.0f / fmaxf(__ldg(cnt + idx), 1.0f);
            float xs[8] = {xa.x, xa.y, xa.z, xa.w, xb.x, xb.y, xb.z, xb.w};
            float ms[8] = {ma.x*iv, ma.y*iv, ma.z*iv, ma.w*iv, mb.x*iv, mb.y*iv, mb.z*iv, mb.w*iv};
            float y[NOUT];
            #pragma unroll
            for (int o = 0; o < NOUT; o++) y[o] = 0.f;
            #pragma unroll
            for (int f = 0; f < 8; f++) {
                float a = xs[f], b = ms[f];
                #pragma unroll
                for (int o = 0; o < NOUT; o++)
                    y[o] = fmaf(a, Ga[f * 10 + o], fmaf(b, Gb[f * 10 + o], y[o]));
            }
            float4* yo = (float4*)(Y + (size_t)idx * 12);
            yo[0] = make_float4(y[0], y[1], y[2], y[3]);
            yo[1] = make_float4(y[4], y[5], y[6], y[7]);
            yo[2] = make_float4(y[8], y[9], 0.f, 0.f);
        }
    }
    gbar(3);

    // ---- P2: lean edge scatter: Z[d] += y[s] ----
    for (int e0 = bid * NTHR + tid; e0 < ET; e0 += nbl * NTHR) {
        int e = e0;
        const int *src, *dst;
        const float* Y;
        float* Z;
        if (e < EM) {
            src = em_src; dst = em_dst; Y = g_yc; Z = scr + OFF_ZC;
        } else {
            e -= EM;
            src = ei_src; dst = ei_dst; Y = g_yp; Z = scr + OFF_ZP;
        }
        int s = __ldg(src + e);
        int d = __ldg(dst + e);
        const float4* py = (const float4*)(Y + (size_t)s * 12);
        float4 y0 = py[0], y1 = py[1], y2 = py[2];
        float* zr = Z + (size_t)d * 12;
        red_add_v4(zr,     y0.x, y0.y, y0.z, y0.w);
        red_add_v4(zr + 4, y1.x, y1.y, y1.z, y1.w);
        red_add_v2(zr + 8, y2.x, y2.y);
    }
    gbar(4);

    // ---- P4: final linear model + softmax (sG/sg already resident) ----
    for (int t = bid * NTHR + tid; t < NT; t += nbl * NTHR) {
        float cm = scr[OFF_CMT + t], ci = scr[OFF_CIT + t];
        float im = 1.f / fmaxf(cm, 1.f);
        float ii = 1.f / fmaxf(ci, 1.f);
        float dm = cm > 0.f ? 1.f : 0.f;
        float di = ci > 0.f ? 1.f : 0.f;

        float p[NOUT];
        #pragma unroll
        for (int o = 0; o < NOUT; o++) {
            float s = sg[40 + o];
            s = fmaf(dm, sg[o]      + sg[20 + o], s);
            s = fmaf(di, sg[10 + o] + sg[30 + o], s);
            p[o] = s;
        }
        {
            const float4* zc = (const float4*)(scr + OFF_ZC + (size_t)t * 12);
            float4 v = zc[0];
            p[0] = fmaf(im, v.x, p[0]); p[1] = fmaf(im, v.y, p[1]);
            p[2] = fmaf(im, v.z, p[2]); p[3] = fmaf(im, v.w, p[3]);
            v = zc[1];
            p[4] = fmaf(im, v.x, p[4]); p[5] = fmaf(im, v.y, p[5]);
            p[6] = fmaf(im, v.z, p[6]); p[7] = fmaf(im, v.w, p[7]);
            v = zc[2];
            p[8] = fmaf(im, v.x, p[8]); p[9] = fmaf(im, v.y, p[9]);
            const float4* zp = (const float4*)(scr + OFF_ZP + (size_t)t * 12);
            v = zp[0];
            p[0] = fmaf(ii, v.x, p[0]); p[1] = fmaf(ii, v.y, p[1]);
            p[2] = fmaf(ii, v.z, p[2]); p[3] = fmaf(ii, v.w, p[3]);
            v = zp[1];
            p[4] = fmaf(ii, v.x, p[4]); p[5] = fmaf(ii, v.y, p[5]);
            p[6] = fmaf(ii, v.z, p[6]); p[7] = fmaf(ii, v.w, p[7]);
            v = zp[2];
            p[8] = fmaf(ii, v.x, p[8]); p[9] = fmaf(ii, v.y, p[9]);
        }
        {
            const float4* px = (const float4*)(x_t + (size_t)t * 8);
            float4 xa = px[0], xb = px[1];
            float xs[8] = {xa.x, xa.y, xa.z, xa.w, xb.x, xb.y, xb.z, xb.w};
            #pragma unroll
            for (int f = 0; f < 8; f++) {
                float xv = xs[f];
                #pragma unroll
                for (int o = 0; o < NOUT; o++) p[o] = fmaf(xv, sG[f * 10 + o], p[o]);
            }
        }

        float m = p[0];
        #pragma unroll
        for (int o = 1; o < NOUT; o++) m = fmaxf(m, p[o]);
        float sum = 0.f;
        #pragma unroll
        for (int o = 0; o < NOUT; o++) { p[o] = expf(p[o] - m); sum += p[o]; }
        float isum = 1.0f / sum;
        #pragma unroll
        for (int o = 0; o < NOUT; o++) out[(size_t)t * NOUT + o] = p[o] * isum;
    }
}

// ---------------- host orchestration ----------------
extern "C" void kernel_launch(void* const* d_in, const int* in_sizes, int n_in,
                              void* d_out, int out_size) {
    const float* x_c   = (const float*)d_in[0];
    const float* x_t   = (const float*)d_in[1];
    const float* x_p   = (const float*)d_in[2];
    const float* W_col = (const float*)d_in[3];
    const float* b_col = (const float*)d_in[4];
    const float* Wn    = (const float*)d_in[5];
    const float* Wr    = (const float*)d_in[6];
    const float* b_lin = (const float*)d_in[7];
    const float* W_out = (const float*)d_in[8];
    const float* b_out = (const float*)d_in[9];
    const int* em_src  = (const int*)d_in[10];
    const int* em_dst  = (const int*)d_in[11];
    const int* ei_src  = (const int*)d_in[12];
    const int* ei_dst  = (const int*)d_in[13];
    float* out = (float*)d_out;

    // co-residency-safe grid size: 6 CTAs per SM, queried at launch (host-side, capture-safe)
    int dev = 0, sms = 148;
    cudaGetDevice(&dev);
    cudaDeviceGetAttribute(&sms, cudaDevAttrMultiProcessorCount, dev);
    int ncta = sms * CTAS_PER_SM;

    unsigned* bar_addr;
    cudaGetSymbolAddress((void**)&bar_addr, g_bar);
    cudaMemsetAsync(bar_addr, 0, sizeof(unsigned));

    fused<<<ncta, NTHR>>>(x_c, x_t, x_p, W_col, b_col, Wn, Wr, b_lin,
                          W_out, b_out, em_src, em_dst, ei_src, ei_dst, out);
}

// round 17
// speedup vs baseline: 1.3664x; 1.3664x over previous
#include <cuda_runtime.h>

// ---------------- problem sizes ----------------
#define NC 100000
#define NT 300000
#define NP 50000
#define EM 300000
#define EI 600000
#define ET (EM + EI)
#define NOUT 10

#define NTHR 256
#define CTAS_PER_SM 6

// ---------------- scratch layout ----------------
#define OFF_MCS   0                               // [NC*8]
#define OFF_MPS   (OFF_MCS + (size_t)NC * 8)      // [NP*8]
#define OFF_CMC   (OFF_MPS + (size_t)NP * 8)      // [NC]
#define OFF_CIP   (OFF_CMC + NC)                  // [NP]
#define OFF_CMT   (OFF_CIP + NP)                  // [NT]
#define OFF_CIT   (OFF_CMT + NT)                  // [NT]
#define ZONEA_END (OFF_CIT + NT)
#define OFF_ZC    ZONEA_END                       // [NT*12]
#define OFF_ZP    (OFF_ZC + (size_t)NT * 12)      // [NT*12]
#define SCR_TOTAL (OFF_ZP + (size_t)NT * 12)

__device__ float g_scr[SCR_TOTAL];
__device__ float g_yc[(size_t)NC * 12];
__device__ float g_yp[(size_t)NP * 12];
__device__ unsigned g_bar;

__device__ float g_m1[7][1024];
__device__ float g_r1[7][128];
__device__ float g_MW[3][1280];
__device__ float g_G[400];
__device__ float g_g[50];

// ---------------- grid barrier ----------------
__device__ __forceinline__ void gbar(int phase) {
    __syncthreads();
    if (threadIdx.x == 0) {
        __threadfence();
        atomicAdd(&g_bar, 1u);
        unsigned target = (unsigned)phase * gridDim.x;
        while (*(volatile unsigned*)&g_bar < target) { __nanosleep(64); }
        __threadfence();
    }
    __syncthreads();
}

// ---------------- atomics ----------------
__device__ __forceinline__ void red_add_v4(float* addr, float a, float b, float c, float d) {
    asm volatile("red.global.add.v4.f32 [%0], {%1,%2,%3,%4};"
                 :: "l"(addr), "f"(a), "f"(b), "f"(c), "f"(d) : "memory");
}
__device__ __forceinline__ void red_add_v2(float* addr, float a, float b) {
    asm volatile("red.global.add.v2.f32 [%0], {%1,%2};"
                 :: "l"(addr), "f"(a), "f"(b) : "memory");
}
__device__ __forceinline__ void red_add_f(float* addr, float v) {
    asm volatile("red.global.add.f32 [%0], %1;" :: "l"(addr), "f"(v) : "memory");
}

// ---------------- prep1 ----------------
__device__ void prep1_block(int b, int col,
                            const float* __restrict__ Wc, const float* __restrict__ bc,
                            const float* __restrict__ Wn, const float* __restrict__ Wr,
                            const float* __restrict__ bl) {
    if (b < 7) {
        int X = 0; const float* M1 = Wn; const float* M2 = nullptr; float s = 1.f;
        switch (b) {
            case 0: X = 1; M1 = Wr;             M2 = Wr + 2 * 16384; s = 0.5f; break;
            case 1: X = 0; M1 = Wn;             s = 0.5f; break;
            case 2: X = 2; M1 = Wn + 2 * 16384; s = 0.5f; break;
            case 3: X = 0; M1 = Wr + 1 * 16384; break;
            case 4: X = 1; M1 = Wn + 1 * 16384; break;
            case 5: X = 2; M1 = Wr + 3 * 16384; break;
            case 6: X = 1; M1 = Wn + 3 * 16384; break;
        }
        for (int f = 0; f < 8; f++) {
            float acc = 0.f;
            #pragma unroll 4
            for (int d = 0; d < 16; d++) {
                int k = f * 16 + d;
                float m = M1[k * 128 + col];
                if (M2) m += M2[k * 128 + col];
                acc += Wc[X * 128 + k] * m;
            }
            g_m1[b][f * 128 + col] = s * acc;
        }
    } else {
        int r = b - 7;
        float acc = 0.f;
        switch (r) {
            case 0:
                for (int k = 0; k < 128; k++) acc += bc[k] * Wn[k * 128 + col];
                g_r1[0][col] = 0.5f * acc; break;
            case 1:
                for (int k = 0; k < 128; k++) acc += bc[256 + k] * Wn[2 * 16384 + k * 128 + col];
                g_r1[1][col] = 0.5f * acc; break;
            case 2:
                for (int k = 0; k < 128; k++)
                    acc += bc[128 + k] * (Wr[k * 128 + col] + Wr[2 * 16384 + k * 128 + col]);
                g_r1[2][col] = 0.5f * (acc + bl[0 * 128 + col] + bl[2 * 128 + col]); break;
            case 3:
                for (int k = 0; k < 128; k++) acc += bc[128 + k] * Wn[1 * 16384 + k * 128 + col];
                g_r1[3][col] = acc; break;
            case 4:
                for (int k = 0; k < 128; k++) acc += bc[k] * Wr[1 * 16384 + k * 128 + col];
                g_r1[4][col] = acc + bl[1 * 128 + col]; break;
            case 5:
                for (int k = 0; k < 128; k++) acc += bc[128 + k] * Wn[3 * 16384 + k * 128 + col];
                g_r1[5][col] = acc; break;
            case 6:
                for (int k = 0; k < 128; k++) acc += bc[256 + k] * Wr[3 * 16384 + k * 128 + col];
                g_r1[6][col] = acc + bl[3 * 128 + col]; break;
        }
    }
}

// ---------------- MW = 0.5*{Un, Vn, R0+R2} @ Wout ----------------
__device__ void mw_thread(int i, const float* __restrict__ Wn, const float* __restrict__ Wr,
                          const float* __restrict__ Wout) {
    int type = i / 1280;
    int rem  = i % 1280;
    int j = rem / 10, o = rem % 10;
    const float* Un = Wn + 4 * 16384;
    const float* Vn = Wn + 6 * 16384;
    const float* R0 = Wr + 4 * 16384;
    const float* R2 = Wr + 6 * 16384;
    float acc = 0.f;
    #pragma unroll 8
    for (int k = 0; k < 128; k++) {
        float m;
        if (type == 0)      m = Un[j * 128 + k];
        else if (type == 1) m = Vn[j * 128 + k];
        else                m = R0[j * 128 + k] + R2[j * 128 + k];
        acc += 0.5f * m * Wout[k * 10 + o];
    }
    g_MW[type][j * 10 + o] = acc;
}

// ---------------- G/g (warp-per-output) ----------------
__device__ void gg_warp(int w, int lane,
                        const float* __restrict__ bl, const float* __restrict__ Wout,
                        const float* __restrict__ bout) {
    float acc = 0.f;
    if (w < 400) {
        int m = w / 80, f = (w % 80) / 10, o = w % 10;
        for (int j = lane; j < 128; j += 32) {
            float v = 0.f;
            switch (m) {
                case 0: v = g_m1[0][f * 128 + j] * g_MW[2][j * 10 + o]; break;
                case 1: v = g_m1[3][f * 128 + j] * g_MW[0][j * 10 + o]
                          + g_m1[1][f * 128 + j] * g_MW[2][j * 10 + o]; break;
                case 2: v = g_m1[5][f * 128 + j] * g_MW[1][j * 10 + o]
                          + g_m1[2][f * 128 + j] * g_MW[2][j * 10 + o]; break;
                case 3: v = g_m1[4][f * 128 + j] * g_MW[0][j * 10 + o]; break;
                case 4: v = g_m1[6][f * 128 + j] * g_MW[1][j * 10 + o]; break;
            }
            acc += v;
        }
        #pragma unroll
        for (int off = 16; off > 0; off >>= 1) acc += __shfl_xor_sync(0xffffffffu, acc, off);
        if (lane == 0) g_G[(m * 8 + f) * 10 + o] = acc;
    } else if (w < 450) {
        int r = (w - 400) / 10, o = (w - 400) % 10;
        for (int j = lane; j < 128; j += 32) {
            float v = 0.f;
            switch (r) {
                case 0: v = g_r1[3][j] * g_MW[0][j * 10 + o]; break;
                case 1: v = g_r1[5][j] * g_MW[1][j * 10 + o]; break;
                case 2: v = g_r1[4][j] * g_MW[0][j * 10 + o] + g_r1[0][j] * g_MW[2][j * 10 + o]; break;
                case 3: v = g_r1[6][j] * g_MW[1][j * 10 + o] + g_r1[1][j] * g_MW[2][j * 10 + o]; break;
                case 4: v = g_r1[2][j] * g_MW[2][j * 10 + o]
                          + 0.5f * (bl[512 + j] + bl[768 + j]) * Wout[j * 10 + o]; break;
            }
            acc += v;
        }
        #pragma unroll
        for (int off = 16; off > 0; off >>= 1) acc += __shfl_xor_sync(0xffffffffu, acc, off);
        if (lane == 0) g_g[r * 10 + o] = acc + (r == 4 ? bout[o] : 0.f);
    }
}

// ---------------- persistent kernel (phases P0..P2; final separate) ----------------
__global__ __launch_bounds__(NTHR, CTAS_PER_SM)
void fused(const float* __restrict__ x_c, const float* __restrict__ x_t,
           const float* __restrict__ x_p,
           const float* __restrict__ W_col, const float* __restrict__ b_col,
           const float* __restrict__ Wn, const float* __restrict__ Wr,
           const float* __restrict__ b_lin,
           const float* __restrict__ W_out, const float* __restrict__ b_out,
           const int* __restrict__ em_src, const int* __restrict__ em_dst,
           const int* __restrict__ ei_src, const int* __restrict__ ei_dst) {
    const int tid = threadIdx.x;
    const int bid = blockIdx.x;
    const int nbl = gridDim.x;
    float* scr = g_scr;
    __shared__ float sG[400];

    // ---- P0: prep1 (0-13) | MW (14-28) | zero zone A (29+) ----
    if (bid < 14) {
        if (tid < 128) prep1_block(bid, tid, W_col, b_col, Wn, Wr, b_lin);
    } else if (bid < 29) {
        int i = (bid - 14) * NTHR + tid;
        if (i < 3840) mw_thread(i, Wn, Wr, W_out);
    } else {
        float4 z = make_float4(0.f, 0.f, 0.f, 0.f);
        float4* p = (float4*)scr;
        int n4 = (int)(ZONEA_END / 4);
        for (int i = (bid - 29) * NTHR + tid; i < n4; i += (nbl - 29) * NTHR) p[i] = z;
    }
    gbar(1);

    // ---- P1: zero zone B + gg_warp (CTAs 0-56, then join) + edge scatter (ALL CTAs) ----
    {
        float4 z = make_float4(0.f, 0.f, 0.f, 0.f);
        float4* p = (float4*)(scr + ZONEA_END);
        int n4 = (int)((SCR_TOTAL - ZONEA_END) / 4);
        for (int i = bid * NTHR + tid; i < n4; i += nbl * NTHR) p[i] = z;
    }
    if (bid < 57) {
        int w = bid * (NTHR / 32) + (tid >> 5);
        gg_warp(w, tid & 31, b_lin, W_out, b_out);
    }
    for (int e0 = bid * NTHR + tid; e0 < ET; e0 += nbl * NTHR) {
        int e = e0;
        const int *src, *dst;
        float *agg, *cnts, *cntd;
        if (e < EM) {
            src = em_src; dst = em_dst;
            agg = scr + OFF_MCS; cnts = scr + OFF_CMC; cntd = scr + OFF_CMT;
        } else {
            e -= EM;
            src = ei_src; dst = ei_dst;
            agg = scr + OFF_MPS; cnts = scr + OFF_CIP; cntd = scr + OFF_CIT;
        }
        int s = __ldg(src + e);
        int d = __ldg(dst + e);
        const float4* pd = (const float4*)(x_t + (size_t)d * 8);
        float4 b0 = pd[0], b1 = pd[1];
        float* os = agg + (size_t)s * 8;
        red_add_v4(os,     b0.x, b0.y, b0.z, b0.w);
        red_add_v4(os + 4, b1.x, b1.y, b1.z, b1.w);
        red_add_f(cnts + s, 1.0f);
        red_add_f(cntd + d, 1.0f);
    }
    gbar(2);

    // ---- P1.5: load G to smem + per-node projection y ----
    for (int i = tid; i < 400; i += NTHR) sG[i] = g_G[i];
    __syncthreads();
    {
        int n = bid * NTHR + tid;
        if (n < NC + NP) {
            const float* xrow;
            const float* msum;
            const float* cnt;
            const float* Ga; const float* Gb;
            float* Y;
            int idx = n;
            if (n < NC) {
                xrow = x_c; msum = scr + OFF_MCS; cnt = scr + OFF_CMC;
                Ga = sG + 80;  Gb = sG + 240;
                Y = g_yc;
            } else {
                idx = n - NC;
                xrow = x_p; msum = scr + OFF_MPS; cnt = scr + OFF_CIP;
                Ga = sG + 160; Gb = sG + 320;
                Y = g_yp;
            }
            const float4* px = (const float4*)(xrow + (size_t)idx * 8);
            const float4* pm = (const float4*)(msum + (size_t)idx * 8);
            float4 xa = px[0], xb = px[1];
            float4 ma = pm[0], mb = pm[1];
            float iv = 1.0f / fmaxf(__ldg(cnt + idx), 1.0f);
            float xs[8] = {xa.x, xa.y, xa.z, xa.w, xb.x, xb.y, xb.z, xb.w};
            float ms[8] = {ma.x*iv, ma.y*iv, ma.z*iv, ma.w*iv, mb.x*iv, mb.y*iv, mb.z*iv, mb.w*iv};
            float y[NOUT];
            #pragma unroll
            for (int o = 0; o < NOUT; o++) y[o] = 0.f;
            #pragma unroll
            for (int f = 0; f < 8; f++) {
                float a = xs[f], b = ms[f];
                #pragma unroll
                for (int o = 0; o < NOUT; o++)
                    y[o] = fmaf(a, Ga[f * 10 + o], fmaf(b, Gb[f * 10 + o], y[o]));
            }
            float4* yo = (float4*)(Y + (size_t)idx * 12);
            yo[0] = make_float4(y[0], y[1], y[2], y[3]);
            yo[1] = make_float4(y[4], y[5], y[6], y[7]);
            yo[2] = make_float4(y[8], y[9], 0.f, 0.f);
        }
    }
    gbar(3);

    // ---- P2: lean edge scatter: Z[d] += y[s] ----
    for (int e0 = bid * NTHR + tid; e0 < ET; e0 += nbl * NTHR) {
        int e = e0;
        const int *src, *dst;
        const float* Y;
        float* Z;
        if (e < EM) {
            src = em_src; dst = em_dst; Y = g_yc; Z = scr + OFF_ZC;
        } else {
            e -= EM;
            src = ei_src; dst = ei_dst; Y = g_yp; Z = scr + OFF_ZP;
        }
        int s = __ldg(src + e);
        int d = __ldg(dst + e);
        const float4* py = (const float4*)(Y + (size_t)s * 12);
        float4 y0 = py[0], y1 = py[1], y2 = py[2];
        float* zr = Z + (size_t)d * 12;
        red_add_v4(zr,     y0.x, y0.y, y0.z, y0.w);
        red_add_v4(zr + 4, y1.x, y1.y, y1.z, y1.w);
        red_add_v2(zr + 8, y2.x, y2.y);
    }
}

// ---------------- final: x_t@G0 + im*Zc + ii*Zp + gates + softmax ----------------
__global__ __launch_bounds__(256, 6)
void final_kernel(const float* __restrict__ xt, float* __restrict__ out) {
    __shared__ float sG0[80];
    __shared__ float sg[50];
    int tid = threadIdx.x;
    if (tid < 80) sG0[tid] = g_G[tid];
    if (tid < 50) sg[tid] = g_g[tid];
    __syncthreads();

    int t = blockIdx.x * 256 + tid;
    if (t >= NT) return;

    float cm = g_scr[OFF_CMT + t], ci = g_scr[OFF_CIT + t];
    float im = 1.f / fmaxf(cm, 1.f);
    float ii = 1.f / fmaxf(ci, 1.f);
    float dm = cm > 0.f ? 1.f : 0.f;
    float di = ci > 0.f ? 1.f : 0.f;

    float p[NOUT];
    #pragma unroll
    for (int o = 0; o < NOUT; o++) {
        float s = sg[40 + o];
        s = fmaf(dm, sg[o]      + sg[20 + o], s);
        s = fmaf(di, sg[10 + o] + sg[30 + o], s);
        p[o] = s;
    }
    {
        const float4* zc = (const float4*)(g_scr + OFF_ZC + (size_t)t * 12);
        float4 v = zc[0];
        p[0] = fmaf(im, v.x, p[0]); p[1] = fmaf(im, v.y, p[1]);
        p[2] = fmaf(im, v.z, p[2]); p[3] = fmaf(im, v.w, p[3]);
        v = zc[1];
        p[4] = fmaf(im, v.x, p[4]); p[5] = fmaf(im, v.y, p[5]);
        p[6] = fmaf(im, v.z, p[6]); p[7] = fmaf(im, v.w, p[7]);
        v = zc[2];
        p[8] = fmaf(im, v.x, p[8]); p[9] = fmaf(im, v.y, p[9]);
        const float4* zp = (const float4*)(g_scr + OFF_ZP + (size_t)t * 12);
        v = zp[0];
        p[0] = fmaf(ii, v.x, p[0]); p[1] = fmaf(ii, v.y, p[1]);
        p[2] = fmaf(ii, v.z, p[2]); p[3] = fmaf(ii, v.w, p[3]);
        v = zp[1];
        p[4] = fmaf(ii, v.x, p[4]); p[5] = fmaf(ii, v.y, p[5]);
        p[6] = fmaf(ii, v.z, p[6]); p[7] = fmaf(ii, v.w, p[7]);
        v = zp[2];
        p[8] = fmaf(ii, v.x, p[8]); p[9] = fmaf(ii, v.y, p[9]);
    }
    {
        const float4* px = (const float4*)(xt + (size_t)t * 8);
        float4 xa = px[0], xb = px[1];
        float xs[8] = {xa.x, xa.y, xa.z, xa.w, xb.x, xb.y, xb.z, xb.w};
        #pragma unroll
        for (int f = 0; f < 8; f++) {
            float xv = xs[f];
            #pragma unroll
            for (int o = 0; o < NOUT; o++) p[o] = fmaf(xv, sG0[f * 10 + o], p[o]);
        }
    }

    float m = p[0];
    #pragma unroll
    for (int o = 1; o < NOUT; o++) m = fmaxf(m, p[o]);
    float sum = 0.f;
    #pragma unroll
    for (int o = 0; o < NOUT; o++) { p[o] = expf(p[o] - m); sum += p[o]; }
    float isum = 1.0f / sum;
    #pragma unroll
    for (int o = 0; o < NOUT; o++) out[(size_t)t * NOUT + o] = p[o] * isum;
}

// ---------------- host orchestration ----------------
extern "C" void kernel_launch(void* const* d_in, const int* in_sizes, int n_in,
                              void* d_out, int out_size) {
    const float* x_c   = (const float*)d_in[0];
    const float* x_t   = (const float*)d_in[1];
    const float* x_p   = (const float*)d_in[2];
    const float* W_col = (const float*)d_in[3];
    const float* b_col = (const float*)d_in[4];
    const float* Wn    = (const float*)d_in[5];
    const float* Wr    = (const float*)d_in[6];
    const float* b_lin = (const float*)d_in[7];
    const float* W_out = (const float*)d_in[8];
    const float* b_out = (const float*)d_in[9];
    const int* em_src  = (const int*)d_in[10];
    const int* em_dst  = (const int*)d_in[11];
    const int* ei_src  = (const int*)d_in[12];
    const int* ei_dst  = (const int*)d_in[13];
    float* out = (float*)d_out;

    int dev = 0, sms = 148;
    cudaGetDevice(&dev);
    cudaDeviceGetAttribute(&sms, cudaDevAttrMultiProcessorCount, dev);
    int ncta = sms * CTAS_PER_SM;

    unsigned* bar_addr;
    cudaGetSymbolAddress((void**)&bar_addr, g_bar);
    cudaMemsetAsync(bar_addr, 0, sizeof(unsigned));

    fused<<<ncta, NTHR>>>(x_c, x_t, x_p, W_col, b_col, Wn, Wr, b_lin,
                          W_out, b_out, em_src, em_dst, ei_src, ei_dst);
    final_kernel<<<(NT + 255) / 256, 256>>>(x_t, out);
}